// round 6
// baseline (speedup 1.0000x reference)
#include <cuda_runtime.h>
#include <cuda_fp16.h>
#include <cstdint>

#define NN 20000
#define EE 320000
#define DD 256
#define CAP 64                      // bucket capacity per row (P(deg>64) ~ 1e-15)

// ---- device scratch (no allocs allowed) ----
// g_cnt starts zero (static init) and is reset to zero by k_spmm each call,
// so no zeroing pass is needed and the build kernel has no internal ordering.
__device__ int    g_cnt[2][NN];             // per-row counts (scatter cursors)
__device__ int2   g_bkt[2][NN * CAP];       // bucketed edges {col, bitcast fp32 val}, 20.5 MB
__device__ __half g_xh[NN * DD];            // fp16 copy of x (10 MB)

// ---- 1) fused: scatter edges into buckets (blocks [0, scB)) and
//              convert x->fp16 (blocks [scB, scB+cvtB)) ----
__global__ void __launch_bounds__(256) k_build(
        const float* __restrict__ x,
        const int* __restrict__ row1, const int* __restrict__ col1,
        const float* __restrict__ val1,
        const int* __restrict__ row2, const int* __restrict__ col2,
        const float* __restrict__ val2, int E, int scB) {
    if ((int)blockIdx.x < scB) {
        // ---- scatter: 4 edges per thread ----
        int t = blockIdx.x * blockDim.x + threadIdx.x;
        int q = E / 4;                         // threads per adjacency
        int a, base;
        const int *rowp, *colp;
        const float *valp;
        if (t < q)          { a = 0; base = t * 4;       rowp = row1; colp = col1; valp = val1; }
        else if (t < 2 * q) { a = 1; base = (t - q) * 4; rowp = row2; colp = col2; valp = val2; }
        else return;

        int4   r4 = __ldg((const int4*)(rowp + base));
        int4   c4 = __ldg((const int4*)(colp + base));
        float4 v4 = __ldg((const float4*)(valp + base));

        int rr[4] = {r4.x, r4.y, r4.z, r4.w};
        int cc[4] = {c4.x, c4.y, c4.z, c4.w};
        float vv[4] = {v4.x, v4.y, v4.z, v4.w};

#pragma unroll
        for (int i = 0; i < 4; i++) {
            int r = rr[i];
            int p = atomicAdd(&g_cnt[a][r], 1);
            if (p < CAP)
                g_bkt[a][r * CAP + p] = make_int2(cc[i], __float_as_int(vv[i]));
        }
    } else {
        // ---- cvt: x -> fp16, 4 floats per thread ----
        int i = (blockIdx.x - scB) * blockDim.x + threadIdx.x;
        if (i >= NN * DD / 4) return;
        float4 f = ((const float4*)x)[i];
        __half2 h0 = __floats2half2_rn(f.x, f.y);
        __half2 h1 = __floats2half2_rn(f.z, f.w);
        uint2 u;
        u.x = *(unsigned*)&h0;
        u.y = *(unsigned*)&h1;
        ((uint2*)g_xh)[i] = u;
    }
}

// ---- 2) SpMM: one warp per (row, adjacency); fp16 gather, fp32 accumulate.
//         Also resets g_cnt to 0 for the next invocation. ----
__global__ void __launch_bounds__(256) k_spmm(float* __restrict__ out, int n) {
    int gw = (blockIdx.x * blockDim.x + threadIdx.x) >> 5;
    int lane = threadIdx.x & 31;
    if (gw >= 2 * n) return;
    int a = (gw >= n) ? 1 : 0;
    int r = gw - a * n;
    int cnt = g_cnt[a][r];
    if (lane == 0) g_cnt[a][r] = 0;         // restore invariant for next replay
    if (cnt > CAP) cnt = CAP;
    const int2* ed = g_bkt[a] + r * CAP;
    const uint4* xh = (const uint4*)g_xh;   // 32 uint4 (= 256 halves) per row

    float acc[8];
#pragma unroll
    for (int i = 0; i < 8; i++) acc[i] = 0.f;

    int k = 0;
    for (; k + 2 <= cnt; k += 2) {
        int4 e2 = __ldg((const int4*)(ed + k));      // two edges, one 16B broadcast
        float v0 = __int_as_float(e2.y);
        float v1 = __int_as_float(e2.w);
        uint4 b0 = __ldg((const uint4*)(xh + (size_t)e2.x * 32) + lane);
        uint4 b1 = __ldg((const uint4*)(xh + (size_t)e2.z * 32) + lane);
        {
            float2 f0 = __half22float2(*(__half2*)&b0.x);
            float2 f1 = __half22float2(*(__half2*)&b0.y);
            float2 f2 = __half22float2(*(__half2*)&b0.z);
            float2 f3 = __half22float2(*(__half2*)&b0.w);
            acc[0] += v0 * f0.x; acc[1] += v0 * f0.y;
            acc[2] += v0 * f1.x; acc[3] += v0 * f1.y;
            acc[4] += v0 * f2.x; acc[5] += v0 * f2.y;
            acc[6] += v0 * f3.x; acc[7] += v0 * f3.y;
        }
        {
            float2 f0 = __half22float2(*(__half2*)&b1.x);
            float2 f1 = __half22float2(*(__half2*)&b1.y);
            float2 f2 = __half22float2(*(__half2*)&b1.z);
            float2 f3 = __half22float2(*(__half2*)&b1.w);
            acc[0] += v1 * f0.x; acc[1] += v1 * f0.y;
            acc[2] += v1 * f1.x; acc[3] += v1 * f1.y;
            acc[4] += v1 * f2.x; acc[5] += v1 * f2.y;
            acc[6] += v1 * f3.x; acc[7] += v1 * f3.y;
        }
    }
    if (k < cnt) {
        int2 ep = __ldg(&ed[k]);
        float v = __int_as_float(ep.y);
        uint4 b = __ldg((const uint4*)(xh + (size_t)ep.x * 32) + lane);
        float2 f0 = __half22float2(*(__half2*)&b.x);
        float2 f1 = __half22float2(*(__half2*)&b.y);
        float2 f2 = __half22float2(*(__half2*)&b.z);
        float2 f3 = __half22float2(*(__half2*)&b.w);
        acc[0] += v * f0.x; acc[1] += v * f0.y;
        acc[2] += v * f1.x; acc[3] += v * f1.y;
        acc[4] += v * f2.x; acc[5] += v * f2.y;
        acc[6] += v * f3.x; acc[7] += v * f3.y;
    }

    float4* o = (float4*)(out + (size_t)r * (2 * DD) + (size_t)a * DD + lane * 8);
    o[0] = make_float4(acc[0], acc[1], acc[2], acc[3]);
    o[1] = make_float4(acc[4], acc[5], acc[6], acc[7]);
}

extern "C" void kernel_launch(void* const* d_in, const int* in_sizes, int n_in,
                              void* d_out, int out_size) {
    const float* x    = (const float*)d_in[0];
    const int*   row1 = (const int*)  d_in[1];
    const int*   col1 = (const int*)  d_in[2];
    const float* val1 = (const float*)d_in[3];
    const int*   row2 = (const int*)  d_in[4];
    const int*   col2 = (const int*)  d_in[5];
    const float* val2 = (const float*)d_in[6];
    float* out = (float*)d_out;

    int n = in_sizes[0] / DD;   // 20000
    int E = in_sizes[1];        // 320000

    int scB  = (2 * (E / 4) + 255) / 256;        // scatter blocks
    int cvtB = (NN * DD / 4 + 255) / 256;        // cvt blocks
    k_build<<<scB + cvtB, 256>>>(x, row1, col1, val1, row2, col2, val2, E, scB);

    int warps = 2 * n;
    int blocks = (warps * 32 + 255) / 256;
    k_spmm<<<blocks, 256>>>(out, n);
}

// round 7
// speedup vs baseline: 1.8379x; 1.8379x over previous
#include <cuda_runtime.h>
#include <cuda_fp16.h>
#include <cstdint>

#define NN 20000
#define EE 320000
#define DD 256
#define CAP 64                      // bucket capacity per row (P(deg>64) ~ 1e-15)

// ---- device scratch (no allocs allowed) ----
__device__ int    g_cnt[2][NN];             // per-row counts (scatter cursors)
__device__ int2   g_bkt[2][NN * CAP];       // bucketed edges {col, bitcast fp32 val}, 20.5 MB
__device__ __half g_xh[NN * DD];            // fp16 copy of x (10 MB)

// ---- 1) zero counters + convert x to fp16 (8 floats/thread) ----
__global__ void __launch_bounds__(256) k_prep(const float* __restrict__ x) {
    int i = blockIdx.x * blockDim.x + threadIdx.x;
    // zero g_cnt: 2*NN ints = 10000 int4
    if (i < (2 * NN) / 4)
        ((int4*)g_cnt)[i] = make_int4(0, 0, 0, 0);
    // cvt: 8 floats -> 8 halves per thread
    if (i < NN * DD / 8) {
        const float4* xp = (const float4*)x + i * 2;
        float4 fa = __ldg(&xp[0]);
        float4 fb = __ldg(&xp[1]);
        __half2 h0 = __floats2half2_rn(fa.x, fa.y);
        __half2 h1 = __floats2half2_rn(fa.z, fa.w);
        __half2 h2 = __floats2half2_rn(fb.x, fb.y);
        __half2 h3 = __floats2half2_rn(fb.z, fb.w);
        uint4 u;
        u.x = *(unsigned*)&h0;
        u.y = *(unsigned*)&h1;
        u.z = *(unsigned*)&h2;
        u.w = *(unsigned*)&h3;
        ((uint4*)g_xh)[i] = u;
    }
}

// ---- 2) scatter into buckets, 8 edges per thread ----
__global__ void __launch_bounds__(256) k_scatter(
        const int* __restrict__ row1, const int* __restrict__ col1,
        const float* __restrict__ val1,
        const int* __restrict__ row2, const int* __restrict__ col2,
        const float* __restrict__ val2, int E) {
    int t = blockIdx.x * blockDim.x + threadIdx.x;
    int q = E / 8;                         // threads per adjacency
    int a, base;
    const int *rowp, *colp;
    const float *valp;
    if (t < q)          { a = 0; base = t * 8;       rowp = row1; colp = col1; valp = val1; }
    else if (t < 2 * q) { a = 1; base = (t - q) * 8; rowp = row2; colp = col2; valp = val2; }
    else return;

    int4   ra = __ldg((const int4*)(rowp + base));
    int4   rb = __ldg((const int4*)(rowp + base + 4));
    int4   ca = __ldg((const int4*)(colp + base));
    int4   cb = __ldg((const int4*)(colp + base + 4));
    float4 va = __ldg((const float4*)(valp + base));
    float4 vb = __ldg((const float4*)(valp + base + 4));

    int rr[8] = {ra.x, ra.y, ra.z, ra.w, rb.x, rb.y, rb.z, rb.w};
    int cc[8] = {ca.x, ca.y, ca.z, ca.w, cb.x, cb.y, cb.z, cb.w};
    float vv[8] = {va.x, va.y, va.z, va.w, vb.x, vb.y, vb.z, vb.w};

#pragma unroll
    for (int i = 0; i < 8; i++) {
        int r = rr[i];
        int p = atomicAdd(&g_cnt[a][r], 1);
        if (p < CAP)
            g_bkt[a][r * CAP + p] = make_int2(cc[i], __float_as_int(vv[i]));
    }
}

// ---- 3) SpMM: one warp per (row, adjacency); fp16 gather, fp32 accumulate.
//         (R5-exact hot loop — no stores besides the final output.) ----
__global__ void __launch_bounds__(256) k_spmm(float* __restrict__ out, int n) {
    int gw = (blockIdx.x * blockDim.x + threadIdx.x) >> 5;
    int lane = threadIdx.x & 31;
    if (gw >= 2 * n) return;
    int a = (gw >= n) ? 1 : 0;
    int r = gw - a * n;
    int cnt = g_cnt[a][r];
    if (cnt > CAP) cnt = CAP;
    const int2* ed = g_bkt[a] + r * CAP;
    const uint4* xh = (const uint4*)g_xh;   // 32 uint4 (= 256 halves) per row

    float acc[8];
#pragma unroll
    for (int i = 0; i < 8; i++) acc[i] = 0.f;

    int k = 0;
    for (; k + 2 <= cnt; k += 2) {
        int4 e2 = __ldg((const int4*)(ed + k));      // two edges, one 16B broadcast
        float v0 = __int_as_float(e2.y);
        float v1 = __int_as_float(e2.w);
        uint4 b0 = __ldg((const uint4*)(xh + (size_t)e2.x * 32) + lane);
        uint4 b1 = __ldg((const uint4*)(xh + (size_t)e2.z * 32) + lane);
        {
            float2 f0 = __half22float2(*(__half2*)&b0.x);
            float2 f1 = __half22float2(*(__half2*)&b0.y);
            float2 f2 = __half22float2(*(__half2*)&b0.z);
            float2 f3 = __half22float2(*(__half2*)&b0.w);
            acc[0] += v0 * f0.x; acc[1] += v0 * f0.y;
            acc[2] += v0 * f1.x; acc[3] += v0 * f1.y;
            acc[4] += v0 * f2.x; acc[5] += v0 * f2.y;
            acc[6] += v0 * f3.x; acc[7] += v0 * f3.y;
        }
        {
            float2 f0 = __half22float2(*(__half2*)&b1.x);
            float2 f1 = __half22float2(*(__half2*)&b1.y);
            float2 f2 = __half22float2(*(__half2*)&b1.z);
            float2 f3 = __half22float2(*(__half2*)&b1.w);
            acc[0] += v1 * f0.x; acc[1] += v1 * f0.y;
            acc[2] += v1 * f1.x; acc[3] += v1 * f1.y;
            acc[4] += v1 * f2.x; acc[5] += v1 * f2.y;
            acc[6] += v1 * f3.x; acc[7] += v1 * f3.y;
        }
    }
    if (k < cnt) {
        int2 ep = __ldg(&ed[k]);
        float v = __int_as_float(ep.y);
        uint4 b = __ldg((const uint4*)(xh + (size_t)ep.x * 32) + lane);
        float2 f0 = __half22float2(*(__half2*)&b.x);
        float2 f1 = __half22float2(*(__half2*)&b.y);
        float2 f2 = __half22float2(*(__half2*)&b.z);
        float2 f3 = __half22float2(*(__half2*)&b.w);
        acc[0] += v * f0.x; acc[1] += v * f0.y;
        acc[2] += v * f1.x; acc[3] += v * f1.y;
        acc[4] += v * f2.x; acc[5] += v * f2.y;
        acc[6] += v * f3.x; acc[7] += v * f3.y;
    }

    float4* o = (float4*)(out + (size_t)r * (2 * DD) + (size_t)a * DD + lane * 8);
    o[0] = make_float4(acc[0], acc[1], acc[2], acc[3]);
    o[1] = make_float4(acc[4], acc[5], acc[6], acc[7]);
}

extern "C" void kernel_launch(void* const* d_in, const int* in_sizes, int n_in,
                              void* d_out, int out_size) {
    const float* x    = (const float*)d_in[0];
    const int*   row1 = (const int*)  d_in[1];
    const int*   col1 = (const int*)  d_in[2];
    const float* val1 = (const float*)d_in[3];
    const int*   row2 = (const int*)  d_in[4];
    const int*   col2 = (const int*)  d_in[5];
    const float* val2 = (const float*)d_in[6];
    float* out = (float*)d_out;

    int n = in_sizes[0] / DD;   // 20000
    int E = in_sizes[1];        // 320000

    k_prep<<<(NN * DD / 8 + 255) / 256, 256>>>(x);
    k_scatter<<<(2 * (E / 8) + 255) / 256, 256>>>(row1, col1, val1,
                                                  row2, col2, val2, E);
    int warps = 2 * n;
    int blocks = (warps * 32 + 255) / 256;
    k_spmm<<<blocks, 256>>>(out, n);
}